// round 8
// baseline (speedup 1.0000x reference)
#include <cuda_runtime.h>
#include <cuda_fp16.h>
#include <stdint.h>

#define N_NODES 200000
#define N_DIM   64
#define N_DIM2  (N_DIM / 2)                 // 32 half2 per row
#define N_EDGES 6400000
#define ROW_U4  8                           // 8 uint4 (16B) chunks per 128B fp16 row
#define NB      ((N_NODES + 255) / 256)     // 782 blocks of 256 nodes
#define VAL_Q   16383.0f                    // 14-bit fixed-point scale for edge vals

// ---------------- static scratch (no allocations allowed) ----------------
__device__ unsigned g_edges[N_EDGES];             // packed: col[17:0] | val_q14 << 18
__device__ int   g_rank[N_EDGES];                 // rank of edge within its row
__device__ int   g_counts[N_NODES];
__device__ int   g_row_ptr[N_NODES];
__device__ int   g_block_sums[NB];
__device__ int   g_block_offs[NB];
__device__ __align__(128) __half2 g_e [N_NODES * N_DIM2];   // fp16 copy of emb
__device__ __align__(128) __half2 g_h1[N_NODES * N_DIM2];   // layer-1 output (fp16)
__device__ __align__(128) __half2 g_h2[N_NODES * N_DIM2];   // layer-2 output (fp16)

// ---------------- init: zero counts + fp32->fp16 convert ----------------
__global__ void init_kernel(const float2* __restrict__ emb) {
    int i = blockIdx.x * blockDim.x + threadIdx.x;
    if (i < N_NODES * N_DIM2) g_e[i] = __float22half2_rn(emb[i]);
    if (i < N_NODES)          g_counts[i] = 0;
}

// histogram, 4 edges per thread (vector loads, 4 independent atomics)
__global__ void histogram_kernel(const int4* __restrict__ rows4) {
    int t = blockIdx.x * blockDim.x + threadIdx.x;
    if (t < N_EDGES / 4) {
        const int4 r = __ldg(rows4 + t);
        int4 rk;
        rk.x = atomicAdd(&g_counts[r.x], 1);
        rk.y = atomicAdd(&g_counts[r.y], 1);
        rk.z = atomicAdd(&g_counts[r.z], 1);
        rk.w = atomicAdd(&g_counts[r.w], 1);
        *(int4*)(g_rank + t * 4) = rk;
    }
}

// scan stage 1: per-256-block sums (coalesced)
__global__ void scan_reduce_kernel() {
    int b = blockIdx.x, t = threadIdx.x;
    int idx = b * 256 + t;
    int v = (idx < N_NODES) ? g_counts[idx] : 0;
    for (int o = 16; o > 0; o >>= 1) v += __shfl_down_sync(0xffffffffu, v, o);
    __shared__ int ws[8];
    if ((t & 31) == 0) ws[t >> 5] = v;
    __syncthreads();
    if (t == 0) {
        int s = 0;
        #pragma unroll
        for (int i = 0; i < 8; i++) s += ws[i];
        g_block_sums[b] = s;
    }
}

// scan stage 2: exclusive scan of NB block sums in one block
__global__ void scan_partials_kernel() {
    __shared__ int sh[1024];
    int t = threadIdx.x;
    int v = (t < NB) ? g_block_sums[t] : 0;
    sh[t] = v;
    __syncthreads();
    for (int off = 1; off < 1024; off <<= 1) {
        int x = sh[t];
        int add = (t >= off) ? sh[t - off] : 0;
        __syncthreads();
        sh[t] = x + add;
        __syncthreads();
    }
    if (t < NB) g_block_offs[t] = sh[t] - v;   // exclusive
}

// scan stage 3: block-local exclusive scan + global offset -> row_ptr
__global__ void scan_apply_kernel() {
    int b = blockIdx.x, t = threadIdx.x;
    int idx = b * 256 + t;
    int v = (idx < N_NODES) ? g_counts[idx] : 0;
    int lane = t & 31, w = t >> 5;
    int x = v;
    #pragma unroll
    for (int o = 1; o < 32; o <<= 1) {
        int y = __shfl_up_sync(0xffffffffu, x, o);
        if (lane >= o) x += y;
    }
    __shared__ int wsum[8];
    __shared__ int woff[8];
    if (lane == 31) wsum[w] = x;
    __syncthreads();
    if (t == 0) {
        int run = 0;
        #pragma unroll
        for (int i = 0; i < 8; i++) { woff[i] = run; run += wsum[i]; }
    }
    __syncthreads();
    if (idx < N_NODES) g_row_ptr[idx] = x - v + woff[w] + g_block_offs[b];
}

// scatter: no atomics — 4 edges per thread, 4B packed records
__global__ void scatter_kernel(const int4* __restrict__ rows4,
                               const int4* __restrict__ cols4,
                               const float4* __restrict__ vals4) {
    int t = blockIdx.x * blockDim.x + threadIdx.x;
    if (t < N_EDGES / 4) {
        const int4   r  = __ldg(rows4 + t);
        const int4   c  = __ldg(cols4 + t);
        const float4 v  = __ldg(vals4 + t);
        const int4   rk = *(const int4*)(g_rank + t * 4);
        const int p0 = g_row_ptr[r.x] + rk.x;
        const int p1 = g_row_ptr[r.y] + rk.y;
        const int p2 = g_row_ptr[r.z] + rk.z;
        const int p3 = g_row_ptr[r.w] + rk.w;
        g_edges[p0] = (unsigned)c.x | ((unsigned)__float2int_rn(v.x * VAL_Q) << 18);
        g_edges[p1] = (unsigned)c.y | ((unsigned)__float2int_rn(v.y * VAL_Q) << 18);
        g_edges[p2] = (unsigned)c.z | ((unsigned)__float2int_rn(v.z * VAL_Q) << 18);
        g_edges[p3] = (unsigned)c.w | ((unsigned)__float2int_rn(v.w * VAL_Q) << 18);
    }
}

// ---------------- row-parallel SpMM ----------------
// 1 warp per row. Warp preloads 32 packed edges coalesced (4B each, one LDG.32
// per lane), decodes (c,v) once, then inner loop broadcasts via SHFL and
// gathers 4 rows per iteration:
// lane = g*8 + s ; g = edge slot within quad ; s = 16B chunk of the 128B row.
// LAYER 1: h1 = A*e ; LAYER 2: h2 = A*h1 ; LAYER 3: out = (emb+h1+h2+A*h2)/4
template<int LAYER>
__global__ void __launch_bounds__(256)
spmm_kernel(const uint4* __restrict__ x,     // fp16 rows
            uint4* __restrict__ y,           // fp16 rows (layers 1,2)
            const float4* __restrict__ emb,  // fp32 (layer 3)
            float4* __restrict__ out) {
    int wid  = (blockIdx.x * blockDim.x + threadIdx.x) >> 5;
    int lane = threadIdx.x & 31;
    if (wid >= N_NODES) return;
    const int g = lane >> 3;      // 0..3 : edge slot
    const int s = lane & 7;       // 0..7 : row chunk

    const int start = g_row_ptr[wid];
    const int deg   = g_counts[wid];
    const unsigned* ep = g_edges + start;

    float a0 = 0.f, a1 = 0.f, a2 = 0.f, a3 = 0.f,
          a4 = 0.f, a5 = 0.f, a6 = 0.f, a7 = 0.f;

    for (int base = 0; base < deg; base += 32) {
        const int n = deg - base;
        unsigned pk = 0u;
        if (lane < n) pk = __ldg(ep + base + lane);
        const unsigned c_reg = pk & 0x3FFFFu;
        const float    v_reg = (float)(pk >> 18) * (1.0f / VAL_Q);
        const int m = (n < 32) ? n : 32;
        const int iters = (m + 3) >> 2;           // <= 8
        #pragma unroll 4
        for (int i = 0; i < iters; i++) {
            const int e = (i << 2) + g;
            const unsigned c = __shfl_sync(0xffffffffu, c_reg, e);
            const float    v = __shfl_sync(0xffffffffu, v_reg, e);
            const uint4 q = __ldg(&x[c * ROW_U4 + s]);   // v==0 lanes gather row 0 harmlessly
            const float2 f0 = __half22float2(*(const __half2*)&q.x);
            const float2 f1 = __half22float2(*(const __half2*)&q.y);
            const float2 f2 = __half22float2(*(const __half2*)&q.z);
            const float2 f3 = __half22float2(*(const __half2*)&q.w);
            a0 = fmaf(v, f0.x, a0);  a1 = fmaf(v, f0.y, a1);
            a2 = fmaf(v, f1.x, a2);  a3 = fmaf(v, f1.y, a3);
            a4 = fmaf(v, f2.x, a4);  a5 = fmaf(v, f2.y, a5);
            a6 = fmaf(v, f3.x, a6);  a7 = fmaf(v, f3.y, a7);
        }
    }

    // combine the 4 edge-groups: xor 8 then xor 16 (s preserved)
    #pragma unroll
    for (int off = 8; off <= 16; off <<= 1) {
        a0 += __shfl_xor_sync(0xffffffffu, a0, off);
        a1 += __shfl_xor_sync(0xffffffffu, a1, off);
        a2 += __shfl_xor_sync(0xffffffffu, a2, off);
        a3 += __shfl_xor_sync(0xffffffffu, a3, off);
        a4 += __shfl_xor_sync(0xffffffffu, a4, off);
        a5 += __shfl_xor_sync(0xffffffffu, a5, off);
        a6 += __shfl_xor_sync(0xffffffffu, a6, off);
        a7 += __shfl_xor_sync(0xffffffffu, a7, off);
    }

    if (g == 0) {   // lanes 0..7 write the row
        if (LAYER < 3) {
            __half2 h0 = __floats2half2_rn(a0, a1);
            __half2 h1 = __floats2half2_rn(a2, a3);
            __half2 h2 = __floats2half2_rn(a4, a5);
            __half2 h3 = __floats2half2_rn(a6, a7);
            uint4 q;
            q.x = *(unsigned*)&h0;  q.y = *(unsigned*)&h1;
            q.z = *(unsigned*)&h2;  q.w = *(unsigned*)&h3;
            y[wid * ROW_U4 + s] = q;
        } else {
            const uint4 q1 = __ldg((const uint4*)g_h1 + wid * ROW_U4 + s);
            const uint4 q2 = __ldg((const uint4*)g_h2 + wid * ROW_U4 + s);
            const float2 b0 = __half22float2(*(const __half2*)&q1.x);
            const float2 b1 = __half22float2(*(const __half2*)&q1.y);
            const float2 b2 = __half22float2(*(const __half2*)&q1.z);
            const float2 b3 = __half22float2(*(const __half2*)&q1.w);
            const float2 c0 = __half22float2(*(const __half2*)&q2.x);
            const float2 c1 = __half22float2(*(const __half2*)&q2.y);
            const float2 c2 = __half22float2(*(const __half2*)&q2.z);
            const float2 c3 = __half22float2(*(const __half2*)&q2.w);
            const float4 e0 = __ldg(&emb[wid * 16 + s * 2 + 0]);
            const float4 e1 = __ldg(&emb[wid * 16 + s * 2 + 1]);
            float4 o0, o1;
            o0.x = (e0.x + b0.x + c0.x + a0) * 0.25f;
            o0.y = (e0.y + b0.y + c0.y + a1) * 0.25f;
            o0.z = (e0.z + b1.x + c1.x + a2) * 0.25f;
            o0.w = (e0.w + b1.y + c1.y + a3) * 0.25f;
            o1.x = (e1.x + b2.x + c2.x + a4) * 0.25f;
            o1.y = (e1.y + b2.y + c2.y + a5) * 0.25f;
            o1.z = (e1.z + b3.x + c3.x + a6) * 0.25f;
            o1.w = (e1.w + b3.y + c3.y + a7) * 0.25f;
            out[wid * 16 + s * 2 + 0] = o0;
            out[wid * 16 + s * 2 + 1] = o1;
        }
    }
}

extern "C" void kernel_launch(void* const* d_in, const int* in_sizes, int n_in,
                              void* d_out, int out_size) {
    const float* emb  = (const float*)d_in[0];
    const float* vals = (const float*)d_in[1];
    const int*   rows = (const int*)d_in[2];
    const int*   cols = (const int*)d_in[3];
    float4* out = (float4*)d_out;

    uint4* he;  uint4* h1;  uint4* h2;
    cudaGetSymbolAddress((void**)&he, g_e);
    cudaGetSymbolAddress((void**)&h1, g_h1);
    cudaGetSymbolAddress((void**)&h2, g_h2);

    const int TB = 256;
    const int E4 = N_EDGES / 4;

    // ---- build CSR (4B packed edge records) ----
    init_kernel<<<(N_NODES * N_DIM2 + TB - 1) / TB, TB>>>((const float2*)emb);
    histogram_kernel<<<(E4 + TB - 1) / TB, TB>>>((const int4*)rows);
    scan_reduce_kernel<<<NB, TB>>>();
    scan_partials_kernel<<<1, 1024>>>();
    scan_apply_kernel<<<NB, TB>>>();
    scatter_kernel<<<(E4 + TB - 1) / TB, TB>>>((const int4*)rows, (const int4*)cols,
                                               (const float4*)vals);

    // ---- 3 propagation layers, one warp per row ----
    const int warps_per_block = TB / 32;
    const int grid = (N_NODES + warps_per_block - 1) / warps_per_block;

    spmm_kernel<1><<<grid, TB>>>(he, h1, (const float4*)emb, out);
    spmm_kernel<2><<<grid, TB>>>(h1, h2, (const float4*)emb, out);
    spmm_kernel<3><<<grid, TB>>>(h2, nullptr, (const float4*)emb, out);
}

// round 9
// speedup vs baseline: 1.1903x; 1.1903x over previous
#include <cuda_runtime.h>
#include <cuda_fp16.h>
#include <stdint.h>

#define N_NODES 200000
#define N_DIM   64
#define N_DIM2  (N_DIM / 2)                 // 32 half2 per row
#define N_EDGES 6400000
#define ROW_U4  8                           // 8 uint4 (16B) chunks per 128B fp16 row
#define BUCKET  64                          // fixed slots per row (Poisson(32) tail ~5e-9)
#define SPILL_MAX 8192
#define VAL_Q   16383.0f                    // 14-bit fixed-point scale for edge vals

// ---------------- static scratch (no allocations allowed) ----------------
__device__ unsigned g_edges[N_NODES * BUCKET];    // packed: col[17:0] | val_q14 << 18
__device__ int      g_counts[N_NODES];
__device__ int      g_spill_n;
__device__ int      g_spill_r [SPILL_MAX];
__device__ unsigned g_spill_cv[SPILL_MAX];
__device__ __align__(128) __half2 g_e [N_NODES * N_DIM2];   // fp16 copy of emb
__device__ __align__(128) __half2 g_h1[N_NODES * N_DIM2];   // layer-1 output (fp16)
__device__ __align__(128) __half2 g_h2[N_NODES * N_DIM2];   // layer-2 output (fp16)

// ---------------- init: zero counts + spill + fp32->fp16 convert ----------------
__global__ void init_kernel(const float2* __restrict__ emb) {
    int i = blockIdx.x * blockDim.x + threadIdx.x;
    if (i < N_NODES * N_DIM2) g_e[i] = __float22half2_rn(emb[i]);
    if (i < N_NODES)          g_counts[i] = 0;
    if (i == 0)               g_spill_n = 0;
}

// fused histogram + scatter: one pass over edges, direct bucket write
__global__ void build_kernel(const int4* __restrict__ rows4,
                             const int4* __restrict__ cols4,
                             const float4* __restrict__ vals4) {
    int t = blockIdx.x * blockDim.x + threadIdx.x;
    if (t >= N_EDGES / 4) return;
    const int4   r = __ldg(rows4 + t);
    const int4   c = __ldg(cols4 + t);
    const float4 v = __ldg(vals4 + t);

    const int    rr[4] = {r.x, r.y, r.z, r.w};
    const unsigned pk[4] = {
        (unsigned)c.x | ((unsigned)__float2int_rn(v.x * VAL_Q) << 18),
        (unsigned)c.y | ((unsigned)__float2int_rn(v.y * VAL_Q) << 18),
        (unsigned)c.z | ((unsigned)__float2int_rn(v.z * VAL_Q) << 18),
        (unsigned)c.w | ((unsigned)__float2int_rn(v.w * VAL_Q) << 18)
    };
    #pragma unroll
    for (int k = 0; k < 4; k++) {
        const int rank = atomicAdd(&g_counts[rr[k]], 1);
        if (rank < BUCKET) {
            g_edges[rr[k] * BUCKET + rank] = pk[k];
        } else {
            const int sp = atomicAdd(&g_spill_n, 1);
            if (sp < SPILL_MAX) { g_spill_r[sp] = rr[k]; g_spill_cv[sp] = pk[k]; }
        }
    }
}

// ---------------- spill fix-up (expected empty; correctness safety net) ----------------
// LAYER 1/2: y[r] += v * x[c]  (fp16 atomics)
// LAYER 3:   out[r] += 0.25 * v * x[c]  (fp32 atomics)
template<int LAYER>
__global__ void spill_kernel(const __half2* __restrict__ x,
                             __half2* __restrict__ y,
                             float* __restrict__ out) {
    const int n = g_spill_n;
    if (n <= 0) return;
    const int lane = threadIdx.x & 31;
    const int w    = threadIdx.x >> 5;     // 8 warps, single block
    for (int i = w; i < n && i < SPILL_MAX; i += 8) {
        const int      rr = g_spill_r[i];
        const unsigned pk = g_spill_cv[i];
        const int   c = (int)(pk & 0x3FFFFu);
        const float v = (float)(pk >> 18) * (1.0f / VAL_Q);
        const float2 xv = __half22float2(x[c * N_DIM2 + lane]);
        if (LAYER < 3) {
            atomicAdd(&y[rr * N_DIM2 + lane], __floats2half2_rn(v * xv.x, v * xv.y));
        } else {
            atomicAdd(&out[rr * N_DIM + 2 * lane + 0], 0.25f * v * xv.x);
            atomicAdd(&out[rr * N_DIM + 2 * lane + 1], 0.25f * v * xv.y);
        }
    }
}

// ---------------- row-parallel SpMM ----------------
// 1 warp per row. Bucketed CSR: row r's edges at g_edges[r*64 .. r*64+deg).
// Warp preloads 32 packed edges coalesced, decodes (c,v), inner loop
// broadcasts via SHFL and gathers 4 rows per iteration:
// lane = g*8 + s ; g = edge slot within quad ; s = 16B chunk of the 128B row.
// LAYER 1: h1 = A*e ; LAYER 2: h2 = A*h1 ; LAYER 3: out = (emb+h1+h2+A*h2)/4
template<int LAYER>
__global__ void __launch_bounds__(256)
spmm_kernel(const uint4* __restrict__ x,     // fp16 rows
            uint4* __restrict__ y,           // fp16 rows (layers 1,2)
            const float4* __restrict__ emb,  // fp32 (layer 3)
            float4* __restrict__ out) {
    int wid  = (blockIdx.x * blockDim.x + threadIdx.x) >> 5;
    int lane = threadIdx.x & 31;
    if (wid >= N_NODES) return;
    const int g = lane >> 3;      // 0..3 : edge slot
    const int s = lane & 7;       // 0..7 : row chunk

    int deg = g_counts[wid];
    if (deg > BUCKET) deg = BUCKET;          // overflow handled by spill kernel
    const unsigned* ep = g_edges + wid * BUCKET;

    float a0 = 0.f, a1 = 0.f, a2 = 0.f, a3 = 0.f,
          a4 = 0.f, a5 = 0.f, a6 = 0.f, a7 = 0.f;

    for (int base = 0; base < deg; base += 32) {
        const int n = deg - base;
        unsigned pk = 0u;
        if (lane < n) pk = __ldg(ep + base + lane);
        const unsigned c_reg = pk & 0x3FFFFu;
        const float    v_reg = (float)(pk >> 18) * (1.0f / VAL_Q);
        const int m = (n < 32) ? n : 32;
        const int iters = (m + 3) >> 2;           // <= 8
        #pragma unroll 2
        for (int i = 0; i < iters; i++) {
            const int e = (i << 2) + g;
            const unsigned c = __shfl_sync(0xffffffffu, c_reg, e);
            const float    v = __shfl_sync(0xffffffffu, v_reg, e);
            const uint4 q = __ldg(&x[c * ROW_U4 + s]);   // v==0 lanes gather row 0 harmlessly
            const float2 f0 = __half22float2(*(const __half2*)&q.x);
            const float2 f1 = __half22float2(*(const __half2*)&q.y);
            const float2 f2 = __half22float2(*(const __half2*)&q.z);
            const float2 f3 = __half22float2(*(const __half2*)&q.w);
            a0 = fmaf(v, f0.x, a0);  a1 = fmaf(v, f0.y, a1);
            a2 = fmaf(v, f1.x, a2);  a3 = fmaf(v, f1.y, a3);
            a4 = fmaf(v, f2.x, a4);  a5 = fmaf(v, f2.y, a5);
            a6 = fmaf(v, f3.x, a6);  a7 = fmaf(v, f3.y, a7);
        }
    }

    // combine the 4 edge-groups: xor 8 then xor 16 (s preserved)
    #pragma unroll
    for (int off = 8; off <= 16; off <<= 1) {
        a0 += __shfl_xor_sync(0xffffffffu, a0, off);
        a1 += __shfl_xor_sync(0xffffffffu, a1, off);
        a2 += __shfl_xor_sync(0xffffffffu, a2, off);
        a3 += __shfl_xor_sync(0xffffffffu, a3, off);
        a4 += __shfl_xor_sync(0xffffffffu, a4, off);
        a5 += __shfl_xor_sync(0xffffffffu, a5, off);
        a6 += __shfl_xor_sync(0xffffffffu, a6, off);
        a7 += __shfl_xor_sync(0xffffffffu, a7, off);
    }

    if (g == 0) {   // lanes 0..7 write the row
        if (LAYER < 3) {
            __half2 h0 = __floats2half2_rn(a0, a1);
            __half2 h1 = __floats2half2_rn(a2, a3);
            __half2 h2 = __floats2half2_rn(a4, a5);
            __half2 h3 = __floats2half2_rn(a6, a7);
            uint4 q;
            q.x = *(unsigned*)&h0;  q.y = *(unsigned*)&h1;
            q.z = *(unsigned*)&h2;  q.w = *(unsigned*)&h3;
            y[wid * ROW_U4 + s] = q;
        } else {
            const uint4 q1 = __ldg((const uint4*)g_h1 + wid * ROW_U4 + s);
            const uint4 q2 = __ldg((const uint4*)g_h2 + wid * ROW_U4 + s);
            const float2 b0 = __half22float2(*(const __half2*)&q1.x);
            const float2 b1 = __half22float2(*(const __half2*)&q1.y);
            const float2 b2 = __half22float2(*(const __half2*)&q1.z);
            const float2 b3 = __half22float2(*(const __half2*)&q1.w);
            const float2 c0 = __half22float2(*(const __half2*)&q2.x);
            const float2 c1 = __half22float2(*(const __half2*)&q2.y);
            const float2 c2 = __half22float2(*(const __half2*)&q2.z);
            const float2 c3 = __half22float2(*(const __half2*)&q2.w);
            const float4 e0 = __ldg(&emb[wid * 16 + s * 2 + 0]);
            const float4 e1 = __ldg(&emb[wid * 16 + s * 2 + 1]);
            float4 o0, o1;
            o0.x = (e0.x + b0.x + c0.x + a0) * 0.25f;
            o0.y = (e0.y + b0.y + c0.y + a1) * 0.25f;
            o0.z = (e0.z + b1.x + c1.x + a2) * 0.25f;
            o0.w = (e0.w + b1.y + c1.y + a3) * 0.25f;
            o1.x = (e1.x + b2.x + c2.x + a4) * 0.25f;
            o1.y = (e1.y + b2.y + c2.y + a5) * 0.25f;
            o1.z = (e1.z + b3.x + c3.x + a6) * 0.25f;
            o1.w = (e1.w + b3.y + c3.y + a7) * 0.25f;
            out[wid * 16 + s * 2 + 0] = o0;
            out[wid * 16 + s * 2 + 1] = o1;
        }
    }
}

extern "C" void kernel_launch(void* const* d_in, const int* in_sizes, int n_in,
                              void* d_out, int out_size) {
    const float* emb  = (const float*)d_in[0];
    const float* vals = (const float*)d_in[1];
    const int*   rows = (const int*)d_in[2];
    const int*   cols = (const int*)d_in[3];
    float4* out = (float4*)d_out;

    uint4* he;  uint4* h1;  uint4* h2;
    cudaGetSymbolAddress((void**)&he, g_e);
    cudaGetSymbolAddress((void**)&h1, g_h1);
    cudaGetSymbolAddress((void**)&h2, g_h2);

    const int TB = 256;
    const int E4 = N_EDGES / 4;

    // ---- build: init + single fused hist/scatter pass ----
    init_kernel<<<(N_NODES * N_DIM2 + TB - 1) / TB, TB>>>((const float2*)emb);
    build_kernel<<<(E4 + TB - 1) / TB, TB>>>((const int4*)rows, (const int4*)cols,
                                             (const float4*)vals);

    // ---- 3 propagation layers, one warp per row; spill fix-up after each ----
    const int warps_per_block = TB / 32;
    const int grid = (N_NODES + warps_per_block - 1) / warps_per_block;

    spmm_kernel<1><<<grid, TB>>>(he, h1, (const float4*)emb, out);
    spill_kernel<1><<<1, TB>>>((const __half2*)he, (__half2*)h1, nullptr);
    spmm_kernel<2><<<grid, TB>>>(h1, h2, (const float4*)emb, out);
    spill_kernel<2><<<1, TB>>>((const __half2*)h1, (__half2*)h2, nullptr);
    spmm_kernel<3><<<grid, TB>>>(h2, nullptr, (const float4*)emb, out);
    spill_kernel<3><<<1, TB>>>((const __half2*)h2, nullptr, (float*)out);
}